// round 12
// baseline (speedup 1.0000x reference)
#include <cuda_runtime.h>

// Fused MLP [N,2]->64->64->64->1, chaotic logistic-map activation.
// Round 9: TWO points per thread. Weight LDS.128 broadcasts (the measured
// binder: L1=96%, ~2 wavefront-cyc each) now feed 4 FFMA2 instead of 2.
// Inter-layer h staged in per-thread smem slots (no syncs needed) to keep
// register count ~200; final layer keeps h in regs. fma.rn.f32x2 throughout.

#define RCONST 3.82843f
#define WSTRIDE 68  // 64 + 4 pad words; 16B-aligned rows, breaks staging conflicts

typedef unsigned long long u64t;

struct SW {
    float W2t[64 * WSTRIDE];  // W2t[k*WSTRIDE + j] = W2[j][k]
    float W3t[64 * WSTRIDE];
    float W1c0[64], W1c1[64];
    float b1[64], b2[64], b3[64], W4[64];
    float b4;
    float pad[3];
    // per-thread h stage: hs[q*128 + tid] = { packed pair (pt A), packed pair (pt B) }
    alignas(16) ulonglong2 hs[32 * 128];
};

__device__ __forceinline__ u64t pack2(float a, float b) {
    u64t r;
    asm("mov.b64 %0, {%1, %2};" : "=l"(r) : "f"(a), "f"(b));
    return r;
}

// act on a packed pair. iter1 exact rewrite: R*x*(1-x) with x=0.5cos+0.5
// equals fma(cos^2, -R/4, R/4).
__device__ __forceinline__ u64t act2(u64t a, u64t NQR, u64t QR, u64t PR, u64t NR) {
    float lo, hi;
    asm("mov.b64 {%0, %1}, %2;" : "=f"(lo), "=f"(hi) : "l"(a));
    lo = __cosf(lo);
    hi = __cosf(hi);
    u64t c, c2, x1, u, v, r;
    asm("mov.b64 %0, {%1, %2};" : "=l"(c) : "f"(lo), "f"(hi));
    asm("mul.rn.f32x2 %0, %1, %1;" : "=l"(c2) : "l"(c));
    asm("fma.rn.f32x2 %0, %1, %2, %3;" : "=l"(x1) : "l"(c2), "l"(NQR), "l"(QR));
    asm("mul.rn.f32x2 %0, %1, %2;" : "=l"(u) : "l"(x1), "l"(PR));
    asm("mul.rn.f32x2 %0, %1, %2;" : "=l"(v) : "l"(x1), "l"(NR));
    asm("fma.rn.f32x2 %0, %1, %2, %3;" : "=l"(r) : "l"(v), "l"(x1), "l"(u));
    return r;
}

// One 64x64 layer for two points. Reads h pairs from smem stage; either
// stores act results back to the stage (STORE) or returns them in registers.
template <bool STORE>
__device__ __forceinline__ void layer2pt(SW* __restrict__ s, int t,
                                         const float* __restrict__ Wt,
                                         const float* __restrict__ b,
                                         u64t hA[32], u64t hB[32],
                                         u64t NQR, u64t QR, u64t PR, u64t NR) {
    u64t accA[32], accB[32];
    const u64t* bp = reinterpret_cast<const u64t*>(b);
#pragma unroll
    for (int q = 0; q < 32; ++q) { accA[q] = bp[q]; accB[q] = bp[q]; }

#pragma unroll
    for (int q = 0; q < 32; ++q) {  // two k-values (2q, 2q+1) per step
        const ulonglong2 hq = s->hs[q * 128 + t];  // {A pair, B pair}
        float aLo, aHi, bLo, bHi;
        asm("mov.b64 {%0, %1}, %2;" : "=f"(aLo), "=f"(aHi) : "l"(hq.x));
        asm("mov.b64 {%0, %1}, %2;" : "=f"(bLo), "=f"(bHi) : "l"(hq.y));
        u64t hA0, hA1, hB0, hB1;
        asm("mov.b64 %0, {%1, %1};" : "=l"(hA0) : "f"(aLo));
        asm("mov.b64 %0, {%1, %1};" : "=l"(hA1) : "f"(aHi));
        asm("mov.b64 %0, {%1, %1};" : "=l"(hB0) : "f"(bLo));
        asm("mov.b64 %0, {%1, %1};" : "=l"(hB1) : "f"(bHi));
        const ulonglong2* rowA = reinterpret_cast<const ulonglong2*>(Wt + (2 * q) * WSTRIDE);
        const ulonglong2* rowB = reinterpret_cast<const ulonglong2*>(Wt + (2 * q + 1) * WSTRIDE);
#pragma unroll
        for (int p = 0; p < 16; ++p) {
            const ulonglong2 wa = rowA[p];  // 4 weights (k=2q), feeds 4 FFMA2
            asm("fma.rn.f32x2 %0, %1, %2, %0;" : "+l"(accA[2 * p])     : "l"(hA0), "l"(wa.x));
            asm("fma.rn.f32x2 %0, %1, %2, %0;" : "+l"(accA[2 * p + 1]) : "l"(hA0), "l"(wa.y));
            asm("fma.rn.f32x2 %0, %1, %2, %0;" : "+l"(accB[2 * p])     : "l"(hB0), "l"(wa.x));
            asm("fma.rn.f32x2 %0, %1, %2, %0;" : "+l"(accB[2 * p + 1]) : "l"(hB0), "l"(wa.y));
            const ulonglong2 wb = rowB[p];  // 4 weights (k=2q+1)
            asm("fma.rn.f32x2 %0, %1, %2, %0;" : "+l"(accA[2 * p])     : "l"(hA1), "l"(wb.x));
            asm("fma.rn.f32x2 %0, %1, %2, %0;" : "+l"(accA[2 * p + 1]) : "l"(hA1), "l"(wb.y));
            asm("fma.rn.f32x2 %0, %1, %2, %0;" : "+l"(accB[2 * p])     : "l"(hB1), "l"(wb.x));
            asm("fma.rn.f32x2 %0, %1, %2, %0;" : "+l"(accB[2 * p + 1]) : "l"(hB1), "l"(wb.y));
        }
    }
#pragma unroll
    for (int q = 0; q < 32; ++q) {
        const u64t rA = act2(accA[q], NQR, QR, PR, NR);
        const u64t rB = act2(accB[q], NQR, QR, PR, NR);
        if (STORE) {
            ulonglong2 v; v.x = rA; v.y = rB;
            s->hs[q * 128 + t] = v;
        } else {
            hA[q] = rA;
            hB[q] = rB;
        }
    }
}

extern __shared__ char smem_raw[];

__global__ void __launch_bounds__(128, 2) Model_17188459119206_kernel(
    const float* __restrict__ x,
    const float* __restrict__ gW1, const float* __restrict__ gb1,
    const float* __restrict__ gW2, const float* __restrict__ gb2,
    const float* __restrict__ gW3, const float* __restrict__ gb3,
    const float* __restrict__ gW4, const float* __restrict__ gb4,
    float* __restrict__ out, int n) {
    SW* s = reinterpret_cast<SW*>(smem_raw);
    const int t = threadIdx.x;

    // Stage weights (W2/W3 transposed).
#pragma unroll
    for (int m = t; m < 4096; m += 128) {
        const int j = m >> 6, k = m & 63;
        s->W2t[k * WSTRIDE + j] = gW2[m];
        s->W3t[k * WSTRIDE + j] = gW3[m];
    }
    if (t < 64) {
        s->W1c0[t] = gW1[2 * t];
        s->W1c1[t] = gW1[2 * t + 1];
        s->b1[t] = gb1[t];
        s->b2[t] = gb2[t];
        s->b3[t] = gb3[t];
        s->W4[t] = gW4[t];
    }
    if (t == 0) s->b4 = gb4[0];
    __syncthreads();

    const int iA = blockIdx.x * 256 + t;
    const int iB = iA + 128;
    if (iA >= n) return;
    const int iBc = (iB < n) ? iB : iA;  // clamp load; store guarded below

    const u64t NQR = pack2(-0.25f * RCONST, -0.25f * RCONST);
    const u64t QR  = pack2(0.25f * RCONST, 0.25f * RCONST);
    const u64t PR  = pack2(RCONST, RCONST);
    const u64t NR  = pack2(-RCONST, -RCONST);

    const float2 pA = reinterpret_cast<const float2*>(x)[iA];
    const float2 pB = reinterpret_cast<const float2*>(x)[iBc];
    u64t pxA, pyA, pxB, pyB;
    asm("mov.b64 %0, {%1, %1};" : "=l"(pxA) : "f"(pA.x));
    asm("mov.b64 %0, {%1, %1};" : "=l"(pyA) : "f"(pA.y));
    asm("mov.b64 %0, {%1, %1};" : "=l"(pxB) : "f"(pB.x));
    asm("mov.b64 %0, {%1, %1};" : "=l"(pyB) : "f"(pB.y));

    // Layer 1: 2 -> 64, both points, straight into the smem stage.
    {
        const u64t* c0 = reinterpret_cast<const u64t*>(s->W1c0);
        const u64t* c1 = reinterpret_cast<const u64t*>(s->W1c1);
        const u64t* bp = reinterpret_cast<const u64t*>(s->b1);
#pragma unroll
        for (int q = 0; q < 32; ++q) {
            const u64t w0 = c0[q], w1 = c1[q], bb = bp[q];
            u64t aA = bb, aB = bb;
            asm("fma.rn.f32x2 %0, %1, %2, %0;" : "+l"(aA) : "l"(pxA), "l"(w0));
            asm("fma.rn.f32x2 %0, %1, %2, %0;" : "+l"(aA) : "l"(pyA), "l"(w1));
            asm("fma.rn.f32x2 %0, %1, %2, %0;" : "+l"(aB) : "l"(pxB), "l"(w0));
            asm("fma.rn.f32x2 %0, %1, %2, %0;" : "+l"(aB) : "l"(pyB), "l"(w1));
            ulonglong2 v;
            v.x = act2(aA, NQR, QR, PR, NR);
            v.y = act2(aB, NQR, QR, PR, NR);
            s->hs[q * 128 + t] = v;
        }
    }

    u64t hA[32], hB[32];
    // Layer 2: results back to stage. Layer 3: results to registers.
    layer2pt<true>(s, t, s->W2t, s->b2, hA, hB, NQR, QR, PR, NR);
    layer2pt<false>(s, t, s->W3t, s->b3, hA, hB, NQR, QR, PR, NR);

    // Layer 4: 64 -> 1, both points.
    u64t dA = pack2(0.0f, 0.0f), dB = pack2(0.0f, 0.0f);
    {
        const u64t* w4 = reinterpret_cast<const u64t*>(s->W4);
#pragma unroll
        for (int q = 0; q < 32; ++q) {
            const u64t w = w4[q];
            asm("fma.rn.f32x2 %0, %1, %2, %0;" : "+l"(dA) : "l"(hA[q]), "l"(w));
            asm("fma.rn.f32x2 %0, %1, %2, %0;" : "+l"(dB) : "l"(hB[q]), "l"(w));
        }
    }
    float aLo, aHi, bLo, bHi;
    asm("mov.b64 {%0, %1}, %2;" : "=f"(aLo), "=f"(aHi) : "l"(dA));
    asm("mov.b64 {%0, %1}, %2;" : "=f"(bLo), "=f"(bHi) : "l"(dB));
    const float sumA = aLo + aHi + s->b4;
    const float sumB = bLo + bHi + s->b4;

    {
        const float c = __cosf(sumA);
        const float x1 = fmaf(c * c, -0.25f * RCONST, 0.25f * RCONST);
        out[iA] = fmaf(-RCONST * x1, x1, RCONST * x1);
    }
    if (iB < n) {
        const float c = __cosf(sumB);
        const float x1 = fmaf(c * c, -0.25f * RCONST, 0.25f * RCONST);
        out[iB] = fmaf(-RCONST * x1, x1, RCONST * x1);
    }
}

extern "C" void kernel_launch(void* const* d_in, const int* in_sizes, int n_in,
                              void* d_out, int out_size) {
    const float* x = (const float*)d_in[0];
    const int n = in_sizes[0] / 2;  // x is [N, 2]

    static int attr_set = 0;
    if (!attr_set) {
        cudaFuncSetAttribute(Model_17188459119206_kernel,
                             cudaFuncAttributeMaxDynamicSharedMemorySize,
                             (int)sizeof(SW));
        attr_set = 1;
    }

    const int threads = 128;
    const int pts_per_block = 256;
    const int blocks = (n + pts_per_block - 1) / pts_per_block;
    Model_17188459119206_kernel<<<blocks, threads, sizeof(SW)>>>(
        x,
        (const float*)d_in[1], (const float*)d_in[2],
        (const float*)d_in[3], (const float*)d_in[4],
        (const float*)d_in[5], (const float*)d_in[6],
        (const float*)d_in[7], (const float*)d_in[8],
        (float*)d_out, n);
}

// round 13
// speedup vs baseline: 1.2679x; 1.2679x over previous
#include <cuda_runtime.h>

// Fused MLP [N,2]->64->64->64->1, chaotic logistic-map activation.
// Round 13: two points/thread (weight-LDS amortization, the R12 idea) but with
// the 64-output layers split into two 32-output halves so only accA[16]+accB[16]
// packed accumulators are live at once (64 regs, not 128) -> no spills.
// h staged in per-thread smem slots (one LDS.128 per k-pair feeds both points).
// Half-0 activations held in registers until half-1 completes, then staged.

#define RCONST 3.82843f
#define WSTRIDE 68  // 64 + 4 pad words; rows 272B = 17*16B (aligned, conflict-breaking)

typedef unsigned long long u64t;

struct SW {
    float W2t[64 * WSTRIDE];  // W2t[k*WSTRIDE + j] = W2[j][k]
    float W3t[64 * WSTRIDE];
    float W1c0[64], W1c1[64];
    float b1[64], b2[64], b3[64], W4[64];
    float b4;
    float pad[3];
    // per-thread h stage: hs[q*128 + tid] = { packed pair (pt A), packed pair (pt B) }
    alignas(16) ulonglong2 hs[32 * 128];
};

__device__ __forceinline__ u64t pack2(float a, float b) {
    u64t r;
    asm("mov.b64 %0, {%1, %2};" : "=l"(r) : "f"(a), "f"(b));
    return r;
}

// act on a packed pair. iter1 exact rewrite: R*x*(1-x) with x=0.5cos+0.5
// equals fma(cos^2, -R/4, R/4).
__device__ __forceinline__ u64t act2(u64t a, u64t NQR, u64t QR, u64t PR, u64t NR) {
    float lo, hi;
    asm("mov.b64 {%0, %1}, %2;" : "=f"(lo), "=f"(hi) : "l"(a));
    lo = __cosf(lo);
    hi = __cosf(hi);
    u64t c, c2, x1, u, v, r;
    asm("mov.b64 %0, {%1, %2};" : "=l"(c) : "f"(lo), "f"(hi));
    asm("mul.rn.f32x2 %0, %1, %1;" : "=l"(c2) : "l"(c));
    asm("fma.rn.f32x2 %0, %1, %2, %3;" : "=l"(x1) : "l"(c2), "l"(NQR), "l"(QR));
    asm("mul.rn.f32x2 %0, %1, %2;" : "=l"(u) : "l"(x1), "l"(PR));
    asm("mul.rn.f32x2 %0, %1, %2;" : "=l"(v) : "l"(x1), "l"(NR));
    asm("fma.rn.f32x2 %0, %1, %2, %3;" : "=l"(r) : "l"(v), "l"(x1), "l"(u));
    return r;
}

// One 64x64 layer for two points, j-split into two halves of 32 outputs.
// Reads h pairs from the smem stage. STORE: write act results back to stage.
// !STORE: return them in hA/hB registers (used for the last 64-wide layer).
template <bool STORE>
__device__ __forceinline__ void layer2pt(SW* __restrict__ s, int t,
                                         const float* __restrict__ Wt,
                                         const float* __restrict__ b,
                                         u64t hA[32], u64t hB[32],
                                         u64t NQR, u64t QR, u64t PR, u64t NR) {
    u64t nA[32], nB[32];  // new activations (half 0 parked here while half 1 runs)
    const u64t* bp = reinterpret_cast<const u64t*>(b);

#pragma unroll
    for (int jh = 0; jh < 2; ++jh) {
        u64t accA[16], accB[16];
#pragma unroll
        for (int p = 0; p < 16; ++p) {
            const u64t bb = bp[16 * jh + p];
            accA[p] = bb;
            accB[p] = bb;
        }

#pragma unroll
        for (int q = 0; q < 32; ++q) {  // k-pair (2q, 2q+1)
            const ulonglong2 hq = s->hs[q * 128 + t];  // {A pair, B pair}, one LDS.128
            float aLo, aHi, bLo, bHi;
            asm("mov.b64 {%0, %1}, %2;" : "=f"(aLo), "=f"(aHi) : "l"(hq.x));
            asm("mov.b64 {%0, %1}, %2;" : "=f"(bLo), "=f"(bHi) : "l"(hq.y));
            u64t hA0, hA1, hB0, hB1;
            asm("mov.b64 %0, {%1, %1};" : "=l"(hA0) : "f"(aLo));
            asm("mov.b64 %0, {%1, %1};" : "=l"(hA1) : "f"(aHi));
            asm("mov.b64 %0, {%1, %1};" : "=l"(hB0) : "f"(bLo));
            asm("mov.b64 %0, {%1, %1};" : "=l"(hB1) : "f"(bHi));
            const ulonglong2* rA =
                reinterpret_cast<const ulonglong2*>(Wt + (2 * q) * WSTRIDE + 32 * jh);
            const ulonglong2* rB =
                reinterpret_cast<const ulonglong2*>(Wt + (2 * q + 1) * WSTRIDE + 32 * jh);
#pragma unroll
            for (int p = 0; p < 8; ++p) {
                const ulonglong2 wa = rA[p];  // 4 weights of row k=2q -> 4 FFMA2
                asm("fma.rn.f32x2 %0, %1, %2, %0;" : "+l"(accA[2 * p])     : "l"(hA0), "l"(wa.x));
                asm("fma.rn.f32x2 %0, %1, %2, %0;" : "+l"(accA[2 * p + 1]) : "l"(hA0), "l"(wa.y));
                asm("fma.rn.f32x2 %0, %1, %2, %0;" : "+l"(accB[2 * p])     : "l"(hB0), "l"(wa.x));
                asm("fma.rn.f32x2 %0, %1, %2, %0;" : "+l"(accB[2 * p + 1]) : "l"(hB0), "l"(wa.y));
                const ulonglong2 wb = rB[p];  // 4 weights of row k=2q+1 -> 4 FFMA2
                asm("fma.rn.f32x2 %0, %1, %2, %0;" : "+l"(accA[2 * p])     : "l"(hA1), "l"(wb.x));
                asm("fma.rn.f32x2 %0, %1, %2, %0;" : "+l"(accA[2 * p + 1]) : "l"(hA1), "l"(wb.y));
                asm("fma.rn.f32x2 %0, %1, %2, %0;" : "+l"(accB[2 * p])     : "l"(hB1), "l"(wb.x));
                asm("fma.rn.f32x2 %0, %1, %2, %0;" : "+l"(accB[2 * p + 1]) : "l"(hB1), "l"(wb.y));
            }
        }

#pragma unroll
        for (int p = 0; p < 16; ++p) {
            nA[16 * jh + p] = act2(accA[p], NQR, QR, PR, NR);
            nB[16 * jh + p] = act2(accB[p], NQR, QR, PR, NR);
        }
    }

#pragma unroll
    for (int q = 0; q < 32; ++q) {
        if (STORE) {
            ulonglong2 v;
            v.x = nA[q];
            v.y = nB[q];
            s->hs[q * 128 + t] = v;  // safe: all reads of old h finished above
        } else {
            hA[q] = nA[q];
            hB[q] = nB[q];
        }
    }
}

extern __shared__ char smem_raw[];

__global__ void __launch_bounds__(128, 2) Model_17188459119206_kernel(
    const float* __restrict__ x,
    const float* __restrict__ gW1, const float* __restrict__ gb1,
    const float* __restrict__ gW2, const float* __restrict__ gb2,
    const float* __restrict__ gW3, const float* __restrict__ gb3,
    const float* __restrict__ gW4, const float* __restrict__ gb4,
    float* __restrict__ out, int n) {
    SW* s = reinterpret_cast<SW*>(smem_raw);
    const int t = threadIdx.x;

    // Stage weights (W2/W3 transposed).
#pragma unroll
    for (int m = t; m < 4096; m += 128) {
        const int j = m >> 6, k = m & 63;
        s->W2t[k * WSTRIDE + j] = gW2[m];
        s->W3t[k * WSTRIDE + j] = gW3[m];
    }
    if (t < 64) {
        s->W1c0[t] = gW1[2 * t];
        s->W1c1[t] = gW1[2 * t + 1];
        s->b1[t] = gb1[t];
        s->b2[t] = gb2[t];
        s->b3[t] = gb3[t];
        s->W4[t] = gW4[t];
    }
    if (t == 0) s->b4 = gb4[0];
    __syncthreads();

    const int iA = blockIdx.x * 256 + t;
    const int iB = iA + 128;
    if (iA >= n) return;
    const int iBc = (iB < n) ? iB : iA;  // clamp load; store guarded below

    const u64t NQR = pack2(-0.25f * RCONST, -0.25f * RCONST);
    const u64t QR  = pack2(0.25f * RCONST, 0.25f * RCONST);
    const u64t PR  = pack2(RCONST, RCONST);
    const u64t NR  = pack2(-RCONST, -RCONST);

    const float2 pA = reinterpret_cast<const float2*>(x)[iA];
    const float2 pB = reinterpret_cast<const float2*>(x)[iBc];
    u64t pxA, pyA, pxB, pyB;
    asm("mov.b64 %0, {%1, %1};" : "=l"(pxA) : "f"(pA.x));
    asm("mov.b64 %0, {%1, %1};" : "=l"(pyA) : "f"(pA.y));
    asm("mov.b64 %0, {%1, %1};" : "=l"(pxB) : "f"(pB.x));
    asm("mov.b64 %0, {%1, %1};" : "=l"(pyB) : "f"(pB.y));

    // Layer 1: 2 -> 64, both points, straight into the smem stage.
    {
        const u64t* c0 = reinterpret_cast<const u64t*>(s->W1c0);
        const u64t* c1 = reinterpret_cast<const u64t*>(s->W1c1);
        const u64t* bp = reinterpret_cast<const u64t*>(s->b1);
#pragma unroll
        for (int q = 0; q < 32; ++q) {
            const u64t w0 = c0[q], w1 = c1[q], bb = bp[q];
            u64t aA = bb, aB = bb;
            asm("fma.rn.f32x2 %0, %1, %2, %0;" : "+l"(aA) : "l"(pxA), "l"(w0));
            asm("fma.rn.f32x2 %0, %1, %2, %0;" : "+l"(aA) : "l"(pyA), "l"(w1));
            asm("fma.rn.f32x2 %0, %1, %2, %0;" : "+l"(aB) : "l"(pxB), "l"(w0));
            asm("fma.rn.f32x2 %0, %1, %2, %0;" : "+l"(aB) : "l"(pyB), "l"(w1));
            ulonglong2 v;
            v.x = act2(aA, NQR, QR, PR, NR);
            v.y = act2(aB, NQR, QR, PR, NR);
            s->hs[q * 128 + t] = v;
        }
    }

    u64t hA[32], hB[32];
    // Layer 2: stage -> stage. Layer 3: stage -> registers.
    layer2pt<true>(s, t, s->W2t, s->b2, hA, hB, NQR, QR, PR, NR);
    layer2pt<false>(s, t, s->W3t, s->b3, hA, hB, NQR, QR, PR, NR);

    // Layer 4: 64 -> 1, both points.
    u64t dA = pack2(0.0f, 0.0f), dB = pack2(0.0f, 0.0f);
    {
        const u64t* w4 = reinterpret_cast<const u64t*>(s->W4);
#pragma unroll
        for (int q = 0; q < 32; ++q) {
            const u64t w = w4[q];
            asm("fma.rn.f32x2 %0, %1, %2, %0;" : "+l"(dA) : "l"(hA[q]), "l"(w));
            asm("fma.rn.f32x2 %0, %1, %2, %0;" : "+l"(dB) : "l"(hB[q]), "l"(w));
        }
    }
    float aLo, aHi, bLo, bHi;
    asm("mov.b64 {%0, %1}, %2;" : "=f"(aLo), "=f"(aHi) : "l"(dA));
    asm("mov.b64 {%0, %1}, %2;" : "=f"(bLo), "=f"(bHi) : "l"(dB));
    const float sumA = aLo + aHi + s->b4;
    const float sumB = bLo + bHi + s->b4;

    {
        const float c = __cosf(sumA);
        const float x1 = fmaf(c * c, -0.25f * RCONST, 0.25f * RCONST);
        out[iA] = fmaf(-RCONST * x1, x1, RCONST * x1);
    }
    if (iB < n) {
        const float c = __cosf(sumB);
        const float x1 = fmaf(c * c, -0.25f * RCONST, 0.25f * RCONST);
        out[iB] = fmaf(-RCONST * x1, x1, RCONST * x1);
    }
}

extern "C" void kernel_launch(void* const* d_in, const int* in_sizes, int n_in,
                              void* d_out, int out_size) {
    const float* x = (const float*)d_in[0];
    const int n = in_sizes[0] / 2;  // x is [N, 2]

    cudaFuncSetAttribute(Model_17188459119206_kernel,
                         cudaFuncAttributeMaxDynamicSharedMemorySize,
                         (int)sizeof(SW));

    const int threads = 128;
    const int pts_per_block = 256;
    const int blocks = (n + pts_per_block - 1) / pts_per_block;
    Model_17188459119206_kernel<<<blocks, threads, sizeof(SW)>>>(
        x,
        (const float*)d_in[1], (const float*)d_in[2],
        (const float*)d_in[3], (const float*)d_in[4],
        (const float*)d_in[5], (const float*)d_in[6],
        (const float*)d_in[7], (const float*)d_in[8],
        (float*)d_out, n);
}